// round 6
// baseline (speedup 1.0000x reference)
#include <cuda_runtime.h>

#define N_IMG 8
#define HH 128
#define WW 128
#define CF 64

typedef unsigned long long ull;

// Scratch buffers (allocation-free workaround per harness rules)
__device__ float g_H[N_IMG * CF * HH * WW];
__device__ float g_A[N_IMG * CF * HH * WW];
__device__ float g_B[N_IMG * CF * HH * WW];
__device__ float g_S[N_IMG * 100 * 256 * 256];

// Pre-transposed weights: per 64-oc chunk, layout [8 stages][72 k][64 oc]
#define WCHUNK (8 * 72 * 64)
__device__ float g_W1[16 * WCHUNK];
__device__ float g_W2[16 * WCHUNK];
__device__ float g_WB[WCHUNK];
__device__ float g_WS[7 * WCHUNK];

__device__ __forceinline__ ull pk2(float lo, float hi) {
    ull r; asm("mov.b64 %0, {%1, %2};" : "=l"(r) : "f"(lo), "f"(hi)); return r;
}
__device__ __forceinline__ void upk2(ull v, float& lo, float& hi) {
    asm("mov.b64 {%0, %1}, %2;" : "=f"(lo), "=f"(hi) : "l"(v));
}
#define FMA2(d, a, b) asm("fma.rn.f32x2 %0, %1, %2, %0;" : "+l"(d) : "l"(a), "l"(b))

// ---------------------------------------------------------------------------
// Weight reformat: src [cout][64][9] (per conv) -> dst [nchunks][8][72][64]
// ---------------------------------------------------------------------------
__global__ __launch_bounds__(256) void reformat_w(
    const float* __restrict__ src, float* __restrict__ dst,
    int cout, int src_conv_stride)
{
    int conv = blockIdx.z, chunk = blockIdx.y, nchunks = gridDim.y;
    const float* s = src + (size_t)conv * src_conv_stride;
    float* d = dst + ((size_t)conv * nchunks + chunk) * WCHUNK;
    int idx = blockIdx.x * 256 + threadIdx.x;
    if (idx >= WCHUNK) return;
    int st = idx / 4608;
    int r  = idx - st * 4608;
    int k  = r >> 6;
    int oc = r & 63;
    int icl = k / 9;
    int tap = k - icl * 9;
    int ic  = st * 8 + icl;
    int ocg = chunk * 64 + oc;
    d[idx] = (ocg < cout) ? s[(ocg * 64 + ic) * 9 + tap] : 0.f;
}

// ---------------------------------------------------------------------------
// Head: out = conv3x3(x - mean, head_w) + head_b      (3 -> 64 channels)
// ---------------------------------------------------------------------------
__global__ __launch_bounds__(256) void head_kernel(
    const float* __restrict__ x, const float* __restrict__ w,
    const float* __restrict__ b, float* __restrict__ out)
{
    int idx = blockIdx.x * 256 + threadIdx.x;
    if (idx >= N_IMG * CF * HH * WW) return;
    int px = idx & (WW - 1);
    int py = (idx >> 7) & (HH - 1);
    int oc = (idx >> 14) & 63;
    int n  = idx >> 20;

    const float mean[3] = {0.4488f * 255.0f, 0.4371f * 255.0f, 0.404f * 255.0f};
    float acc = b[oc];
    #pragma unroll
    for (int ic = 0; ic < 3; ic++) {
        const float* xin = x + ((n * 3 + ic) * HH) * WW;
        const float* wp  = w + (oc * 3 + ic) * 9;
        #pragma unroll
        for (int dy = 0; dy < 3; dy++) {
            int gy = py + dy - 1;
            if ((unsigned)gy >= HH) continue;
            #pragma unroll
            for (int dx = 0; dx < 3; dx++) {
                int gx = px + dx - 1;
                if ((unsigned)gx >= WW) continue;
                acc += (xin[gy * WW + gx] - mean[ic]) * wp[dy * 3 + dx];
            }
        }
    }
    out[idx] = acc;
}

// ---------------------------------------------------------------------------
// Main 3x3 conv, CIN=64. Block = 128 thr = 64 oc x (16w x 8h) tile.
// Thread = 4 oc x 16 px, pixels packed in f32x2 pairs -> fma.rn.f32x2.
// dx=0/2 taps read aligned pairs of in_s; dx=1 reads a 1-shifted copy in_s2.
// Weights pre-transposed -> pure coalesced float4 copy into smem.
// ---------------------------------------------------------------------------
template <bool RELU, bool RES, bool SHUF>
__global__ __launch_bounds__(128) void conv3x3_64(
    const float* __restrict__ in, const float* __restrict__ w,
    const float* __restrict__ bias, const float* __restrict__ res,
    float* __restrict__ out, int cout_total, int oc_chunks)
{
    __shared__ float in_s [8][10][20];   // 18 valid cols (halo), pitch 20
    __shared__ float in_s2[8][10][20];   // shifted by +1 col (17 valid)
    __shared__ float w_s[72 * 64];       // [k][oc], same layout as prepped gmem

    const int tid     = threadIdx.x;
    const int n       = blockIdx.z / oc_chunks;
    const int chunk   = blockIdx.z % oc_chunks;
    const int oc_base = chunk * 64;
    const int x0      = blockIdx.x * 16;
    const int y0      = blockIdx.y * 8;
    const int oc_thr  = tid >> 3;        // 0..15 -> 4 oc
    const int ty      = tid & 7;         // 0..7  -> one 16-wide row

    const float* wbase = w + (size_t)chunk * WCHUNK;

    ull acc[4][8];
    #pragma unroll
    for (int o = 0; o < 4; o++)
        #pragma unroll
        for (int q = 0; q < 8; q++) acc[o][q] = pk2(0.f, 0.f);

    for (int st = 0; st < 8; st++) {
        // input tile (+ shifted copy), zero-padded halo
        for (int idx = tid; idx < 8 * 10 * 18; idx += 128) {
            int icl = idx / 180;
            int rem = idx - icl * 180;
            int r = rem / 18;
            int c = rem - r * 18;
            int gy = y0 + r - 1;
            int gx = x0 + c - 1;
            float v = 0.f;
            if ((unsigned)gy < HH && (unsigned)gx < WW)
                v = in[((n * 64 + st * 8 + icl) * HH + gy) * WW + gx];
            in_s[icl][r][c] = v;
            if (c >= 1) in_s2[icl][r][c - 1] = v;
        }
        // weights: coalesced float4 copy (prepped layout == smem layout)
        {
            const float4* ws4 = (const float4*)(wbase + st * 4608);
            float4* wd4 = (float4*)w_s;
            #pragma unroll
            for (int i = 0; i < 9; i++)
                wd4[tid + i * 128] = ws4[tid + i * 128];
        }
        __syncthreads();

        #pragma unroll 1
        for (int icl = 0; icl < 8; icl++) {
            #pragma unroll
            for (int dy = 0; dy < 3; dy++) {
                const float* row0 = &in_s [icl][ty + dy][0];
                const float* rowS = &in_s2[icl][ty + dy][0];
                const int kb = icl * 9 + dy * 3;

                float4 w0 = *(const float4*)&w_s[(kb + 0) * 64 + oc_thr * 4];
                float4 w1 = *(const float4*)&w_s[(kb + 1) * 64 + oc_thr * 4];
                float4 w2 = *(const float4*)&w_s[(kb + 2) * 64 + oc_thr * 4];
                ull wd0[4] = {pk2(w0.x,w0.x), pk2(w0.y,w0.y), pk2(w0.z,w0.z), pk2(w0.w,w0.w)};
                ull wd1[4] = {pk2(w1.x,w1.x), pk2(w1.y,w1.y), pk2(w1.z,w1.z), pk2(w1.w,w1.w)};
                ull wd2[4] = {pk2(w2.x,w2.x), pk2(w2.y,w2.y), pk2(w2.z,w2.z), pk2(w2.w,w2.w)};

                #pragma unroll
                for (int q = 0; q < 8; q++) {
                    ull iv0 = *(const ull*)(row0 + 2 * q);        // (rv[2q],   rv[2q+1])
                    ull iv1 = *(const ull*)(rowS + 2 * q);        // (rv[2q+1], rv[2q+2])
                    ull iv2 = *(const ull*)(row0 + 2 * q + 2);    // (rv[2q+2], rv[2q+3])
                    #pragma unroll
                    for (int o = 0; o < 4; o++) {
                        FMA2(acc[o][q], wd0[o], iv0);
                        FMA2(acc[o][q], wd1[o], iv1);
                        FMA2(acc[o][q], wd2[o], iv2);
                    }
                }
            }
        }
        __syncthreads();
    }

    // epilogue
    const int yy = y0 + ty;
    #pragma unroll
    for (int o = 0; o < 4; o++) {
        int oc = oc_base + oc_thr * 4 + o;
        if (oc >= cout_total) continue;
        float bv = bias[oc];
        if (SHUF) {
            int k = oc >> 2;
            int a = (oc >> 1) & 1;
            int bb = oc & 1;
            float* op = out + ((n * 100 + k) * 256 + (yy * 2 + a)) * 256 + bb;
            #pragma unroll
            for (int q = 0; q < 8; q++) {
                float v0, v1;
                upk2(acc[o][q], v0, v1);
                v0 += bv; v1 += bv;
                if (RELU) { v0 = fmaxf(v0, 0.f); v1 = fmaxf(v1, 0.f); }
                op[(x0 + 2 * q)     * 2] = v0;
                op[(x0 + 2 * q + 1) * 2] = v1;
            }
        } else {
            float* op = out + ((n * 64 + oc) * HH + yy) * WW + x0;
            const float* rp = RES ? res + ((n * 64 + oc) * HH + yy) * WW + x0 : nullptr;
            #pragma unroll
            for (int q = 0; q < 8; q++) {
                float v0, v1;
                upk2(acc[o][q], v0, v1);
                v0 += bv; v1 += bv;
                if (RELU) { v0 = fmaxf(v0, 0.f); v1 = fmaxf(v1, 0.f); }
                if (RES) {
                    float2 r2 = *(const float2*)(rp + 2 * q);
                    v0 += r2.x; v1 += r2.y;
                }
                float2 v; v.x = v0; v.y = v1;
                *(float2*)(op + 2 * q) = v;
            }
        }
    }
}

// ---------------------------------------------------------------------------
// Tail: y = conv3x3(shuffled, out_w) + out_b + mean    (100 -> 3, 256x256)
// ---------------------------------------------------------------------------
__global__ __launch_bounds__(256) void tail_kernel(
    const float* __restrict__ in, const float* __restrict__ w,
    const float* __restrict__ b, float* __restrict__ out)
{
    __shared__ float w_s[2700];
    for (int i = threadIdx.x; i < 2700; i += 256) w_s[i] = w[i];
    __syncthreads();

    int idx = blockIdx.x * 256 + threadIdx.x;
    int x = idx & 255;
    int y = (idx >> 8) & 255;
    int n = idx >> 16;

    float a0 = b[0], a1 = b[1], a2 = b[2];
    for (int ic = 0; ic < 100; ic++) {
        const float* ip = in + ((n * 100 + ic) * 256) * 256;
        #pragma unroll
        for (int dy = 0; dy < 3; dy++) {
            int gy = y + dy - 1;
            if ((unsigned)gy >= 256) continue;
            #pragma unroll
            for (int dx = 0; dx < 3; dx++) {
                int gx = x + dx - 1;
                if ((unsigned)gx >= 256) continue;
                float v = ip[gy * 256 + gx];
                int t = ic * 9 + dy * 3 + dx;
                a0 += v * w_s[t];
                a1 += v * w_s[900 + t];
                a2 += v * w_s[1800 + t];
            }
        }
    }
    const float m0 = 0.4488f * 255.0f, m1 = 0.4371f * 255.0f, m2 = 0.404f * 255.0f;
    out[((n * 3 + 0) * 256 + y) * 256 + x] = a0 + m0;
    out[((n * 3 + 1) * 256 + y) * 256 + x] = a1 + m1;
    out[((n * 3 + 2) * 256 + y) * 256 + x] = a2 + m2;
}

// ---------------------------------------------------------------------------
extern "C" void kernel_launch(void* const* d_in, const int* in_sizes, int n_in,
                              void* d_out, int out_size)
{
    const float* x       = (const float*)d_in[0];
    const float* head_w  = (const float*)d_in[1];
    const float* head_b  = (const float*)d_in[2];
    const float* rb_w1   = (const float*)d_in[3];
    const float* rb_b1   = (const float*)d_in[4];
    const float* rb_w2   = (const float*)d_in[5];
    const float* rb_b2   = (const float*)d_in[6];
    const float* body_w  = (const float*)d_in[7];
    const float* body_b  = (const float*)d_in[8];
    const float* super_w = (const float*)d_in[9];
    const float* super_b = (const float*)d_in[10];
    const float* out_w   = (const float*)d_in[11];
    const float* out_b   = (const float*)d_in[12];
    float* out = (float*)d_out;

    float *pH, *pA, *pB, *pS, *pW1, *pW2, *pWB, *pWS;
    cudaGetSymbolAddress((void**)&pH, g_H);
    cudaGetSymbolAddress((void**)&pA, g_A);
    cudaGetSymbolAddress((void**)&pB, g_B);
    cudaGetSymbolAddress((void**)&pS, g_S);
    cudaGetSymbolAddress((void**)&pW1, g_W1);
    cudaGetSymbolAddress((void**)&pW2, g_W2);
    cudaGetSymbolAddress((void**)&pWB, g_WB);
    cudaGetSymbolAddress((void**)&pWS, g_WS);

    // weight reformat (tiny)
    dim3 rg(144, 1, 16);
    reformat_w<<<rg, 256>>>(rb_w1, pW1, 64, 64 * 64 * 9);
    reformat_w<<<rg, 256>>>(rb_w2, pW2, 64, 64 * 64 * 9);
    reformat_w<<<dim3(144, 1, 1), 256>>>(body_w, pWB, 64, 0);
    reformat_w<<<dim3(144, 7, 1), 256>>>(super_w, pWS, 400, 0);

    // head
    head_kernel<<<(N_IMG * CF * HH * WW) / 256, 256>>>(x, head_w, head_b, pH);

    dim3 grid(WW / 16, HH / 8, N_IMG);

    // 16 residual blocks: B = relu(conv1(cur)); A = cur + conv2(B)
    const float* cur = pH;
    for (int i = 0; i < 16; i++) {
        conv3x3_64<true, false, false><<<grid, 128>>>(
            cur, pW1 + (size_t)i * WCHUNK, rb_b1 + i * 64, nullptr, pB, 64, 1);
        conv3x3_64<false, true, false><<<grid, 128>>>(
            pB, pW2 + (size_t)i * WCHUNK, rb_b2 + i * 64, cur, pA, 64, 1);
        cur = pA;
    }

    // body: H = conv(A) + H
    conv3x3_64<false, true, false><<<grid, 128>>>(pA, pWB, body_b, pH, pH, 64, 1);

    // super conv 64 -> 400 with fused pixel shuffle (7 oc-chunks of 64)
    dim3 gridS(WW / 16, HH / 8, N_IMG * 7);
    conv3x3_64<false, false, true><<<gridS, 128>>>(pH, pWS, super_b, nullptr, pS, 400, 7);

    // tail conv 100 -> 3 on 256x256 + add mean
    tail_kernel<<<(N_IMG * 256 * 256) / 256, 256>>>(pS, out_w, out_b, out);
}

// round 9
// speedup vs baseline: 1.5202x; 1.5202x over previous
#include <cuda_runtime.h>
#include <cuda_bf16.h>

typedef unsigned int u32;
typedef unsigned short u16;
typedef unsigned long long u64;
typedef __nv_bfloat16 bf16;

#define N_IMG 8
#define HH 128
#define WW 128
#define PLANE (N_IMG*HH*WW*64)
#define CHUNK_W (18*4096)          // bf16 elems per conv-chunk weight block (147456 B)
#define DYN_SMEM 216832

// ---------------- scratch ----------------
__device__ bf16 g_Hh[PLANE], g_Hl[PLANE];
__device__ bf16 g_Ah[PLANE], g_Al[PLANE];
__device__ bf16 g_Bh[PLANE], g_Bl[PLANE];
__device__ float g_Hf[PLANE], g_Af[PLANE];
__device__ float g_S[N_IMG*100*256*256];
__device__ bf16 g_Wp[40*CHUNK_W];

// ---------------- helpers ----------------
__device__ __forceinline__ u32 smem_u32(const void* p){
    u32 a; asm("{ .reg .u64 t; cvta.to.shared.u64 t, %1; cvt.u32.u64 %0, t; }":"=r"(a):"l"(p)); return a;
}
__device__ __forceinline__ void ldsm4(u32* r, u32 addr){
    asm volatile("ldmatrix.sync.aligned.m8n8.x4.shared.b16 {%0,%1,%2,%3}, [%4];"
        : "=r"(r[0]),"=r"(r[1]),"=r"(r[2]),"=r"(r[3]) : "r"(addr));
}
__device__ __forceinline__ void ldsm4t(u32* r, u32 addr){
    asm volatile("ldmatrix.sync.aligned.m8n8.x4.trans.shared.b16 {%0,%1,%2,%3}, [%4];"
        : "=r"(r[0]),"=r"(r[1]),"=r"(r[2]),"=r"(r[3]) : "r"(addr));
}
__device__ __forceinline__ void mma_bf16(float* c, const u32* a, const u32* b){
    asm volatile("mma.sync.aligned.m16n8k16.row.col.f32.bf16.bf16.f32 "
        "{%0,%1,%2,%3}, {%4,%5,%6,%7}, {%8,%9}, {%0,%1,%2,%3};"
        : "+f"(c[0]),"+f"(c[1]),"+f"(c[2]),"+f"(c[3])
        : "r"(a[0]),"r"(a[1]),"r"(a[2]),"r"(a[3]), "r"(b[0]),"r"(b[1]));
}

// ---------------- weight prepack ----------------
// per 64-oc chunk: 18 tiles [tap(9)][plane(2)], tile = [ic 64][oc 64] bf16,
// swizzled: byte = ic*128 + ((oc>>3)^(ic&7))*16 + (oc&7)*2
__global__ __launch_bounds__(256) void prepack_w(
    const float* __restrict__ src, bf16* __restrict__ dst,
    int cout, int conv_stride, int nchunks)
{
    int conv = blockIdx.z, chunk = blockIdx.y;
    int idx = blockIdx.x*256 + threadIdx.x;
    if (idx >= CHUNK_W) return;
    int tile = idx >> 12, r = idx & 4095;
    int oc = r >> 6, ic = r & 63;
    int tap = tile >> 1, pl = tile & 1;
    int dy = tap/3, dx = tap%3;
    int ocg = chunk*64 + oc;
    float wv = (ocg < cout) ? src[(size_t)conv*conv_stride + ((size_t)ocg*64 + ic)*9 + dy*3 + dx] : 0.f;
    bf16 h = __float2bfloat16(wv);
    bf16 v = pl ? __float2bfloat16(wv - __bfloat162float(h)) : h;
    int elem = tile*4096 + ic*64 + ((((oc>>3) ^ (ic&7)) << 3) | (oc & 7));
    dst[(size_t)(conv*nchunks + chunk)*CHUNK_W + elem] = v;
}

// ---------------- head: 3->64 fp32, out NHWC hi/lo/f32 ----------------
__global__ __launch_bounds__(256) void head_tc(
    const float* __restrict__ x, const float* __restrict__ w, const float* __restrict__ b,
    bf16* __restrict__ oh, bf16* __restrict__ ol, float* __restrict__ of)
{
    __shared__ float w_s[64*27];
    for (int i = threadIdx.x; i < 64*27; i += 256) w_s[i] = w[i];
    __syncthreads();
    int idx = blockIdx.x*256 + threadIdx.x;      // over 8*128*128
    int px = idx & 127, y = (idx >> 7) & 127, n = idx >> 14;
    const float mean[3] = {0.4488f*255.f, 0.4371f*255.f, 0.404f*255.f};
    float iv[27];
    #pragma unroll
    for (int ic = 0; ic < 3; ic++)
        #pragma unroll
        for (int dy = 0; dy < 3; dy++)
            #pragma unroll
            for (int dx = 0; dx < 3; dx++) {
                int gy = y + dy - 1, gx = px + dx - 1;
                float v = 0.f;
                if ((unsigned)gy < 128 && (unsigned)gx < 128)
                    v = x[((n*3 + ic)*128 + gy)*128 + gx] - mean[ic];
                iv[ic*9 + dy*3 + dx] = v;
            }
    size_t base = (size_t)idx * 64;
    for (int oc = 0; oc < 64; oc++) {
        float acc = b[oc];
        #pragma unroll
        for (int t = 0; t < 27; t++) acc += iv[t] * w_s[oc*27 + t];
        bf16 h = __float2bfloat16(acc);
        oh[base + oc] = h;
        ol[base + oc] = __float2bfloat16(acc - __bfloat162float(h));
        of[base + oc] = acc;
    }
}

// ---------------- mma.sync conv ----------------
// CTA 128 thr (4 warps). Tile: 64 px (half-row) x 64 oc, strip of 8 rows.
// smem: W 18x8KB resident + A ring 3 rows x (2 planes x 66 px x 128B) + stage + bias.
// Warp w: px [w*16, w*16+16). dx tap = A row offset. 3 split-bf16 terms.
template <bool RELU, bool RES, bool F32O, bool SHUF>
__global__ __launch_bounds__(128, 1) void conv_mma(
    const bf16* __restrict__ in_h, const bf16* __restrict__ in_l,
    const bf16* __restrict__ wp, const float* __restrict__ bias,
    const float* __restrict__ resf,
    bf16* __restrict__ out_h, bf16* __restrict__ out_l,
    float* __restrict__ out_f, float* __restrict__ out_s)
{
    extern __shared__ char dyn[];
    const int tid = threadIdx.x, w = tid >> 5, lane = tid & 31;
    const int y0 = blockIdx.x * 8;
    const int half = blockIdx.y >> 3, n = blockIdx.y & 7;
    const int chunk = blockIdx.z;
    const int px0 = half * 64;

    u32 sb = smem_u32(dyn);
    u32 W_sa = (sb + 127) & ~127u;
    char* W_s = dyn + (W_sa - sb);
    char* A_s = W_s + 147456;
    u32 A_sa = W_sa + 147456;
    float* stage  = (float*)(A_s + 50688);
    float* bias_s = (float*)((char*)stage + 17408);

    // resident weights + bias
    {
        const uint4* ws = (const uint4*)(wp + (size_t)chunk * CHUNK_W);
        uint4* wd = (uint4*)W_s;
        #pragma unroll 8
        for (int i = 0; i < 72; i++) wd[tid + i*128] = ws[tid + i*128];
        if (tid < 64) bias_s[tid] = bias[chunk*64 + tid];
    }

    auto load_row = [&](int rg){
        int slot = ((rg % 3) + 3) % 3;
        char* dst = A_s + slot * 16896;
        bool rok = ((unsigned)rg < 128u);
        for (int i = tid; i < 528; i += 128) {
            int px = i >> 3, c = i & 7;
            int pg = px0 + px - 1;
            uint4 vh = make_uint4(0,0,0,0), vl = make_uint4(0,0,0,0);
            if (rok && (unsigned)pg < 128u) {
                size_t off = ((size_t)((n*128 + rg)*128 + pg))*64 + c*8;
                vh = *(const uint4*)(in_h + off);
                vl = *(const uint4*)(in_l + off);
            }
            int cp = c ^ (px & 7);
            *(uint4*)(dst + px*128 + cp*16) = vh;
            *(uint4*)(dst + 8448 + px*128 + cp*16) = vl;
        }
    };

    load_row(y0 - 1); load_row(y0); load_row(y0 + 1);
    __syncthreads();

    for (int y = y0; y < y0 + 8; y++) {
        float acc[8][4];
        #pragma unroll
        for (int t = 0; t < 8; t++) { acc[t][0]=acc[t][1]=acc[t][2]=acc[t][3]=0.f; }

        #pragma unroll 1
        for (int dy = 0; dy < 3; dy++) {
            int slot = (y + dy + 2) % 3;
            u32 abase = A_sa + slot * 16896;
            #pragma unroll 1
            for (int dx = 0; dx < 3; dx++) {
                int row = w*16 + dx + (lane & 15);
                u32 arow = abase + row * 128;
                u32 tapo = W_sa + (u32)((dy*3 + dx) * 2) * 8192u;
                u32 ah[4][4], al[4][4];
                #pragma unroll
                for (int kc = 0; kc < 4; kc++) {
                    u32 csel = (u32)((((kc << 1) | (lane >> 4)) ^ (row & 7)) << 4);
                    ldsm4(ah[kc], arow + csel);
                    ldsm4(al[kc], arow + 8448 + csel);
                }
                int bk = lane & 15, bsw = bk & 7, bh2 = lane >> 4;
                #pragma unroll
                for (int kc = 0; kc < 4; kc++) {
                    u32 brh = tapo + (u32)(kc*16 + bk) * 128u;
                    u32 brl = brh + 8192u;
                    #pragma unroll
                    for (int np = 0; np < 4; np++) {
                        u32 co = (u32)(((np*2 + bh2) ^ bsw) << 4);
                        u32 bh[4], bl[4];
                        ldsm4t(bh, brh + co);
                        ldsm4t(bl, brl + co);
                        mma_bf16(acc[np*2],   ah[kc], bh);
                        mma_bf16(acc[np*2+1], ah[kc], bh+2);
                        mma_bf16(acc[np*2],   al[kc], bh);
                        mma_bf16(acc[np*2+1], al[kc], bh+2);
                        mma_bf16(acc[np*2],   ah[kc], bl);
                        mma_bf16(acc[np*2+1], ah[kc], bl+2);
                    }
                }
            }
        }

        // stage fragments -> smem (fp32, pitch 68 floats)
        {
            int r0 = w*16 + (lane >> 2);
            int cb = (lane & 3) * 2;
            #pragma unroll
            for (int nt = 0; nt < 8; nt++) {
                int c0 = nt*8 + cb;
                *(float2*)&stage[r0*68 + c0]       = make_float2(acc[nt][0], acc[nt][1]);
                *(float2*)&stage[(r0+8)*68 + c0]   = make_float2(acc[nt][2], acc[nt][3]);
            }
        }
        __syncthreads();

        // vector epilogue: thread = (px, oc-half)
        {
            int px = tid >> 1, oh = (tid & 1) * 32;
            int pg = px0 + px;
            float v[32];
            #pragma unroll
            for (int q = 0; q < 8; q++) {
                float4 t = *(float4*)&stage[px*68 + oh + q*4];
                v[q*4]=t.x; v[q*4+1]=t.y; v[q*4+2]=t.z; v[q*4+3]=t.w;
            }
            #pragma unroll
            for (int i = 0; i < 32; i++) {
                v[i] += bias_s[oh + i];
                if (RELU) v[i] = fmaxf(v[i], 0.f);
            }
            size_t rowbase = ((size_t)((n*128 + y)*128 + pg))*64 + oh;
            if (RES) {
                #pragma unroll
                for (int q = 0; q < 8; q++) {
                    float4 r4 = *(const float4*)(resf + rowbase + q*4);
                    v[q*4]+=r4.x; v[q*4+1]+=r4.y; v[q*4+2]+=r4.z; v[q*4+3]+=r4.w;
                }
            }
            if (SHUF) {
                #pragma unroll
                for (int i = 0; i < 32; i++) {
                    int ocg = chunk*64 + oh + i;
                    if (ocg < 400) {
                        int kk = ocg >> 2, aa = (ocg >> 1) & 1, bb = ocg & 1;
                        out_s[((size_t)(n*100 + kk)*256 + (2*y + aa))*256 + (2*pg + bb)] = v[i];
                    }
                }
            } else {
                u32 hp[16], lp[16];
                #pragma unroll
                for (int j = 0; j < 16; j++) {
                    bf16 h0 = __float2bfloat16(v[2*j]);
                    bf16 h1 = __float2bfloat16(v[2*j+1]);
                    bf16 q0 = __float2bfloat16(v[2*j]   - __bfloat162float(h0));
                    bf16 q1 = __float2bfloat16(v[2*j+1] - __bfloat162float(h1));
                    hp[j] = (u32)__bfloat16_as_ushort(h0) | ((u32)__bfloat16_as_ushort(h1) << 16);
                    lp[j] = (u32)__bfloat16_as_ushort(q0) | ((u32)__bfloat16_as_ushort(q1) << 16);
                }
                uint4* oh4 = (uint4*)(out_h + rowbase);
                uint4* ol4 = (uint4*)(out_l + rowbase);
                #pragma unroll
                for (int q = 0; q < 4; q++) {
                    oh4[q] = make_uint4(hp[q*4], hp[q*4+1], hp[q*4+2], hp[q*4+3]);
                    ol4[q] = make_uint4(lp[q*4], lp[q*4+1], lp[q*4+2], lp[q*4+3]);
                }
                if (F32O) {
                    float4* of4 = (float4*)(out_f + rowbase);
                    #pragma unroll
                    for (int q = 0; q < 8; q++)
                        of4[q] = make_float4(v[q*4], v[q*4+1], v[q*4+2], v[q*4+3]);
                }
            }
        }
        if (y + 2 <= y0 + 8) load_row(y + 2);
        __syncthreads();
    }
}

// ---------------- tail: 100 -> 3 on 256x256, + mean ----------------
__global__ __launch_bounds__(256) void tail_kernel(
    const float* __restrict__ in, const float* __restrict__ w,
    const float* __restrict__ b, float* __restrict__ out)
{
    __shared__ float w_s[2700];
    for (int i = threadIdx.x; i < 2700; i += 256) w_s[i] = w[i];
    __syncthreads();
    int idx = blockIdx.x*256 + threadIdx.x;
    int x = idx & 255, y = (idx >> 8) & 255, n = idx >> 16;
    float a0 = b[0], a1 = b[1], a2 = b[2];
    for (int ic = 0; ic < 100; ic++) {
        const float* ip = in + ((size_t)(n*100 + ic) * 256) * 256;
        #pragma unroll
        for (int dy = 0; dy < 3; dy++) {
            int gy = y + dy - 1;
            if ((unsigned)gy >= 256) continue;
            #pragma unroll
            for (int dx = 0; dx < 3; dx++) {
                int gx = x + dx - 1;
                if ((unsigned)gx >= 256) continue;
                float v = ip[gy*256 + gx];
                int t = ic*9 + dy*3 + dx;
                a0 += v * w_s[t];
                a1 += v * w_s[900 + t];
                a2 += v * w_s[1800 + t];
            }
        }
    }
    out[((size_t)(n*3 + 0)*256 + y)*256 + x] = a0 + 0.4488f*255.f;
    out[((size_t)(n*3 + 1)*256 + y)*256 + x] = a1 + 0.4371f*255.f;
    out[((size_t)(n*3 + 2)*256 + y)*256 + x] = a2 + 0.404f*255.f;
}

// ---------------- launch ----------------
extern "C" void kernel_launch(void* const* d_in, const int* in_sizes, int n_in,
                              void* d_out, int out_size)
{
    const float* x       = (const float*)d_in[0];
    const float* head_w  = (const float*)d_in[1];
    const float* head_b  = (const float*)d_in[2];
    const float* rb_w1   = (const float*)d_in[3];
    const float* rb_b1   = (const float*)d_in[4];
    const float* rb_w2   = (const float*)d_in[5];
    const float* rb_b2   = (const float*)d_in[6];
    const float* body_w  = (const float*)d_in[7];
    const float* body_b  = (const float*)d_in[8];
    const float* super_w = (const float*)d_in[9];
    const float* super_b = (const float*)d_in[10];
    const float* out_w   = (const float*)d_in[11];
    const float* out_b   = (const float*)d_in[12];
    float* out = (float*)d_out;

    bf16 *pHh,*pHl,*pAh,*pAl,*pBh,*pBl,*pW;
    float *pHf,*pAf,*pS;
    cudaGetSymbolAddress((void**)&pHh, g_Hh); cudaGetSymbolAddress((void**)&pHl, g_Hl);
    cudaGetSymbolAddress((void**)&pAh, g_Ah); cudaGetSymbolAddress((void**)&pAl, g_Al);
    cudaGetSymbolAddress((void**)&pBh, g_Bh); cudaGetSymbolAddress((void**)&pBl, g_Bl);
    cudaGetSymbolAddress((void**)&pHf, g_Hf); cudaGetSymbolAddress((void**)&pAf, g_Af);
    cudaGetSymbolAddress((void**)&pS,  g_S);  cudaGetSymbolAddress((void**)&pW,  g_Wp);

    cudaFuncSetAttribute(conv_mma<true,false,false,false>, cudaFuncAttributeMaxDynamicSharedMemorySize, DYN_SMEM);
    cudaFuncSetAttribute(conv_mma<false,true,true,false>,  cudaFuncAttributeMaxDynamicSharedMemorySize, DYN_SMEM);
    cudaFuncSetAttribute(conv_mma<false,true,false,false>, cudaFuncAttributeMaxDynamicSharedMemorySize, DYN_SMEM);
    cudaFuncSetAttribute(conv_mma<false,false,false,true>, cudaFuncAttributeMaxDynamicSharedMemorySize, DYN_SMEM);

    // weight prepack
    prepack_w<<<dim3(288,1,16), 256>>>(rb_w1, pW,                64, 64*64*9, 1);
    prepack_w<<<dim3(288,1,16), 256>>>(rb_w2, pW + 16*CHUNK_W,   64, 64*64*9, 1);
    prepack_w<<<dim3(288,1,1),  256>>>(body_w, pW + (size_t)32*CHUNK_W, 64, 0, 1);
    prepack_w<<<dim3(288,7,1),  256>>>(super_w, pW + (size_t)33*CHUNK_W, 400, 0, 7);

    head_tc<<<(N_IMG*HH*WW)/256, 256>>>(x, head_w, head_b, pHh, pHl, pHf);

    dim3 grid(16, 16, 1);
    const bf16 *ch = pHh, *cl = pHl;
    const float* cf = pHf;
    for (int i = 0; i < 16; i++) {
        conv_mma<true,false,false,false><<<grid, 128, DYN_SMEM>>>(
            ch, cl, pW + (size_t)i*CHUNK_W, rb_b1 + i*64, nullptr,
            pBh, pBl, nullptr, nullptr);
        conv_mma<false,true,true,false><<<grid, 128, DYN_SMEM>>>(
            pBh, pBl, pW + (size_t)(16+i)*CHUNK_W, rb_b2 + i*64, cf,
            pAh, pAl, pAf, nullptr);
        ch = pAh; cl = pAl; cf = pAf;
    }
    // body: conv(A) + H -> B planes
    conv_mma<false,true,false,false><<<grid, 128, DYN_SMEM>>>(
        pAh, pAl, pW + (size_t)32*CHUNK_W, body_b, pHf,
        pBh, pBl, nullptr, nullptr);
    // super: 7 chunks, fused pixel-shuffle -> g_S
    conv_mma<false,false,false,true><<<dim3(16, 16, 7), 128, DYN_SMEM>>>(
        pBh, pBl, pW + (size_t)33*CHUNK_W, super_b, nullptr,
        nullptr, nullptr, nullptr, pS);

    tail_kernel<<<(N_IMG*256*256)/256, 256>>>(pS, out_w, out_b, out);
}

// round 12
// speedup vs baseline: 2.3041x; 1.5157x over previous
#include <cuda_runtime.h>
#include <cuda_bf16.h>

typedef unsigned int u32;
typedef unsigned short u16;
typedef unsigned long long u64;
typedef __nv_bfloat16 bf16;

#define N_IMG 8
#define HH 128
#define WW 128
#define PLANE (N_IMG*HH*WW*64)
#define CHUNK_W (18*4096)          // bf16 elems per conv-chunk weight block (147456 B)
#define RING_SLOT 16896            // one row: 2 planes x 66 px x 128 B
#define DYN_SMEM (147456 + 4*RING_SLOT + 128)

// ---------------- scratch ----------------
__device__ bf16 g_Hh[PLANE], g_Hl[PLANE];
__device__ bf16 g_Ah[PLANE], g_Al[PLANE];
__device__ bf16 g_Bh[PLANE], g_Bl[PLANE];
__device__ float g_Hf[PLANE], g_Af[PLANE];
__device__ float g_S[N_IMG*100*256*256];
__device__ bf16 g_Wp[40*CHUNK_W];

// ---------------- helpers ----------------
__device__ __forceinline__ u32 smem_u32(const void* p){
    u32 a; asm("{ .reg .u64 t; cvta.to.shared.u64 t, %1; cvt.u32.u64 %0, t; }":"=r"(a):"l"(p)); return a;
}
__device__ __forceinline__ void ldsm4(u32* r, u32 addr){
    asm volatile("ldmatrix.sync.aligned.m8n8.x4.shared.b16 {%0,%1,%2,%3}, [%4];"
        : "=r"(r[0]),"=r"(r[1]),"=r"(r[2]),"=r"(r[3]) : "r"(addr));
}
__device__ __forceinline__ void ldsm4t(u32* r, u32 addr){
    asm volatile("ldmatrix.sync.aligned.m8n8.x4.trans.shared.b16 {%0,%1,%2,%3}, [%4];"
        : "=r"(r[0]),"=r"(r[1]),"=r"(r[2]),"=r"(r[3]) : "r"(addr));
}
__device__ __forceinline__ void mma_bf16(float* c, const u32* a, const u32* b){
    asm volatile("mma.sync.aligned.m16n8k16.row.col.f32.bf16.bf16.f32 "
        "{%0,%1,%2,%3}, {%4,%5,%6,%7}, {%8,%9}, {%0,%1,%2,%3};"
        : "+f"(c[0]),"+f"(c[1]),"+f"(c[2]),"+f"(c[3])
        : "r"(a[0]),"r"(a[1]),"r"(a[2]),"r"(a[3]), "r"(b[0]),"r"(b[1]));
}
__device__ __forceinline__ void cp16(u32 dst, const void* src, bool ok){
    int sz = ok ? 16 : 0;
    asm volatile("cp.async.cg.shared.global [%0], [%1], 16, %2;"
        :: "r"(dst), "l"(src), "r"(sz));
}
#define CP_COMMIT() asm volatile("cp.async.commit_group;" ::: "memory")
#define CP_WAIT(n)  asm volatile("cp.async.wait_group %0;" :: "n"(n) : "memory")

// ---------------- weight prepack ----------------
// per 64-oc chunk: 18 tiles [tap(9)][plane(2)], tile = [ic 64][oc 64] bf16,
// swizzled: byte = ic*128 + ((oc>>3)^(ic&7))*16 + (oc&7)*2
__global__ __launch_bounds__(256) void prepack_w(
    const float* __restrict__ src, bf16* __restrict__ dst,
    int cout, int conv_stride, int nchunks)
{
    int conv = blockIdx.z, chunk = blockIdx.y;
    int idx = blockIdx.x*256 + threadIdx.x;
    if (idx >= CHUNK_W) return;
    int tile = idx >> 12, r = idx & 4095;
    int oc = r >> 6, ic = r & 63;
    int tap = tile >> 1, pl = tile & 1;
    int dy = tap/3, dx = tap%3;
    int ocg = chunk*64 + oc;
    float wv = (ocg < cout) ? src[(size_t)conv*conv_stride + ((size_t)ocg*64 + ic)*9 + dy*3 + dx] : 0.f;
    bf16 h = __float2bfloat16(wv);
    bf16 v = pl ? __float2bfloat16(wv - __bfloat162float(h)) : h;
    int elem = tile*4096 + ic*64 + ((((oc>>3) ^ (ic&7)) << 3) | (oc & 7));
    dst[(size_t)(conv*nchunks + chunk)*CHUNK_W + elem] = v;
}

// ---------------- head: 3->64 fp32, out NHWC hi/lo/f32 ----------------
__global__ __launch_bounds__(256) void head_tc(
    const float* __restrict__ x, const float* __restrict__ w, const float* __restrict__ b,
    bf16* __restrict__ oh, bf16* __restrict__ ol, float* __restrict__ of)
{
    __shared__ float w_s[64*27];
    for (int i = threadIdx.x; i < 64*27; i += 256) w_s[i] = w[i];
    __syncthreads();
    int idx = blockIdx.x*256 + threadIdx.x;      // over 8*128*128
    int px = idx & 127, y = (idx >> 7) & 127, n = idx >> 14;
    const float mean[3] = {0.4488f*255.f, 0.4371f*255.f, 0.404f*255.f};
    float iv[27];
    #pragma unroll
    for (int ic = 0; ic < 3; ic++)
        #pragma unroll
        for (int dy = 0; dy < 3; dy++)
            #pragma unroll
            for (int dx = 0; dx < 3; dx++) {
                int gy = y + dy - 1, gx = px + dx - 1;
                float v = 0.f;
                if ((unsigned)gy < 128 && (unsigned)gx < 128)
                    v = x[((n*3 + ic)*128 + gy)*128 + gx] - mean[ic];
                iv[ic*9 + dy*3 + dx] = v;
            }
    size_t base = (size_t)idx * 64;
    for (int oc = 0; oc < 64; oc++) {
        float acc = b[oc];
        #pragma unroll
        for (int t = 0; t < 27; t++) acc += iv[t] * w_s[oc*27 + t];
        bf16 h = __float2bfloat16(acc);
        oh[base + oc] = h;
        ol[base + oc] = __float2bfloat16(acc - __bfloat162float(h));
        of[base + oc] = acc;
    }
}

// ---------------- mma.sync conv v3 ----------------
// CTA 128 thr (4 warps). Tile: 64 px (half-row) x 64 oc, strip of 16 rows.
// 2 output rows per tap sweep; TWO rows prefetched per iteration via cp.async
// groups A (yb+2, issued at start) and B (yb+3, issued after dy=0 frees its
// ring slot). wait_group 2 before dy=1 (row yb+1 = B of prev iter),
// wait_group 1 before dy=2 (row yb+2 = A). Direct register epilogue.
template <bool RELU, bool RES, bool F32O, bool SHUF>
__global__ __launch_bounds__(128, 1) void conv_mma(
    const bf16* __restrict__ in_h, const bf16* __restrict__ in_l,
    const bf16* __restrict__ wp, const float* __restrict__ bias,
    const float* __restrict__ resf,
    bf16* __restrict__ out_h, bf16* __restrict__ out_l,
    float* __restrict__ out_f, float* __restrict__ out_s)
{
    extern __shared__ char dyn[];
    __shared__ float bias_s[64];
    const int tid = threadIdx.x, w = tid >> 5, lane = tid & 31;
    const int y0 = blockIdx.x * 16;
    const int half = blockIdx.y >> 3, n = blockIdx.y & 7;
    const int chunk = blockIdx.z;
    const int px0 = half * 64;

    u32 sb = smem_u32(dyn);
    u32 W_sa = (sb + 127) & ~127u;
    u32 ring_sa = W_sa + 147456;

    // async weight load (147456 B = 72 cp16/thread)
    {
        const char* wsrc = (const char*)(wp + (size_t)chunk * CHUNK_W);
        #pragma unroll 8
        for (int i = tid; i < 9216; i += 128)
            cp16(W_sa + i*16, wsrc + (size_t)i*16, true);
        if (tid < 64) bias_s[tid] = bias[chunk*64 + tid];
    }

    auto load_row = [&](int rg){
        u32 dst0 = ring_sa + (u32)(rg & 3) * RING_SLOT;
        bool rok = ((unsigned)rg < 128u);
        #pragma unroll 2
        for (int i = tid; i < 528; i += 128) {
            int px = i >> 3, c = i & 7;
            int pg = px0 + px - 1;
            bool ok = rok && ((unsigned)pg < 128u);
            size_t off = ok ? (((size_t)((n*128 + rg)*128 + pg))*64 + c*8) : 0;
            u32 d = dst0 + px*128 + ((c ^ (px & 7)) << 4);
            cp16(d, in_h + off, ok);
            cp16(d + 8448, in_l + off, ok);
        }
    };

    load_row(y0 - 1); load_row(y0); load_row(y0 + 1);
    CP_COMMIT();
    CP_WAIT(0);
    __syncthreads();

    const int bk = lane & 15, bsw = bk & 7, bh2 = lane >> 4;

    for (int yb = y0; yb < y0 + 16; yb += 2) {
        load_row(yb + 2);          // group A
        CP_COMMIT();

        float acc[2][8][4];
        #pragma unroll
        for (int rr = 0; rr < 2; rr++)
            #pragma unroll
            for (int t = 0; t < 8; t++)
                acc[rr][t][0]=acc[rr][t][1]=acc[rr][t][2]=acc[rr][t][3]=0.f;

        auto taps = [&](int dy, int s0, int s1){
            u32 sl0 = ring_sa + (u32)s0 * RING_SLOT;
            u32 sl1 = ring_sa + (u32)s1 * RING_SLOT;
            #pragma unroll 1
            for (int dx = 0; dx < 3; dx++) {
                int ar = w*16 + dx + bk;
                u32 arow0 = sl0 + ar*128, arow1 = sl1 + ar*128;
                u32 tapo = W_sa + (u32)((dy*3 + dx) * 2) * 8192u;
                #pragma unroll
                for (int kc = 0; kc < 4; kc++) {
                    u32 csel = (u32)((((kc << 1) | bh2) ^ (ar & 7)) << 4);
                    u32 a0h[4], a0l[4], a1h[4], a1l[4];
                    ldsm4(a0h, arow0 + csel);
                    ldsm4(a0l, arow0 + 8448 + csel);
                    ldsm4(a1h, arow1 + csel);
                    ldsm4(a1l, arow1 + 8448 + csel);
                    u32 brh = tapo + (u32)(kc*16 + bk) * 128u;
                    #pragma unroll
                    for (int np = 0; np < 4; np++) {
                        u32 co = (u32)(((np*2 + bh2) ^ bsw) << 4);
                        u32 bh[4], bl[4];
                        ldsm4t(bh, brh + co);
                        ldsm4t(bl, brh + 8192u + co);
                        mma_bf16(acc[0][np*2],   a0h, bh);
                        mma_bf16(acc[0][np*2+1], a0h, bh+2);
                        mma_bf16(acc[0][np*2],   a0l, bh);
                        mma_bf16(acc[0][np*2+1], a0l, bh+2);
                        mma_bf16(acc[0][np*2],   a0h, bl);
                        mma_bf16(acc[0][np*2+1], a0h, bl+2);
                        mma_bf16(acc[1][np*2],   a1h, bh);
                        mma_bf16(acc[1][np*2+1], a1h, bh+2);
                        mma_bf16(acc[1][np*2],   a1l, bh);
                        mma_bf16(acc[1][np*2+1], a1l, bh+2);
                        mma_bf16(acc[1][np*2],   a1h, bl);
                        mma_bf16(acc[1][np*2+1], a1h, bl+2);
                    }
                }
            }
        };

        // dy=0: input rows yb-1, yb
        taps(0, (yb-1)&3, yb&3);
        __syncthreads();           // dy=0 readers done -> slot (yb+3)&3 free
        load_row(yb + 3);          // group B
        CP_COMMIT();
        CP_WAIT(2);                // row yb+1 (B of prev iter) complete
        __syncthreads();
        // dy=1: input rows yb, yb+1
        taps(1, yb&3, (yb+1)&3);
        CP_WAIT(1);                // row yb+2 (A) complete
        __syncthreads();
        // dy=2: input rows yb+1, yb+2
        taps(2, (yb+1)&3, (yb+2)&3);

        // direct register epilogue
        const int cb = (lane & 3) * 2;
        #pragma unroll
        for (int rr = 0; rr < 2; rr++) {
            int yy = yb + rr;
            #pragma unroll
            for (int h = 0; h < 2; h++) {
                int pg = px0 + w*16 + (lane >> 2) + h*8;
                size_t base = ((size_t)((n*128 + yy)*128 + pg))*64 + cb;
                if (SHUF) {
                    #pragma unroll
                    for (int nt = 0; nt < 8; nt++) {
                        float v0 = acc[rr][nt][2*h]   + bias_s[nt*8 + cb];
                        float v1 = acc[rr][nt][2*h+1] + bias_s[nt*8 + cb + 1];
                        int oc0 = chunk*64 + nt*8 + cb;
                        if (oc0 < 400) {
                            int kk = oc0 >> 2, aa = (oc0 >> 1) & 1, bb = oc0 & 1;
                            out_s[((size_t)(n*100 + kk)*256 + (2*yy + aa))*256 + (2*pg + bb)] = v0;
                        }
                        int oc1 = oc0 + 1;
                        if (oc1 < 400) {
                            int kk = oc1 >> 2, aa = (oc1 >> 1) & 1, bb = oc1 & 1;
                            out_s[((size_t)(n*100 + kk)*256 + (2*yy + aa))*256 + (2*pg + bb)] = v1;
                        }
                    }
                } else {
                    #pragma unroll
                    for (int nt = 0; nt < 8; nt++) {
                        float v0 = acc[rr][nt][2*h]   + bias_s[nt*8 + cb];
                        float v1 = acc[rr][nt][2*h+1] + bias_s[nt*8 + cb + 1];
                        if (RELU) { v0 = fmaxf(v0, 0.f); v1 = fmaxf(v1, 0.f); }
                        if (RES) {
                            float2 r2 = *(const float2*)(resf + base + nt*8);
                            v0 += r2.x; v1 += r2.y;
                        }
                        bf16 h0 = __float2bfloat16(v0);
                        bf16 h1 = __float2bfloat16(v1);
                        bf16 q0 = __float2bfloat16(v0 - __bfloat162float(h0));
                        bf16 q1 = __float2bfloat16(v1 - __bfloat162float(h1));
                        *(u32*)(out_h + base + nt*8) =
                            (u32)__bfloat16_as_ushort(h0) | ((u32)__bfloat16_as_ushort(h1) << 16);
                        *(u32*)(out_l + base + nt*8) =
                            (u32)__bfloat16_as_ushort(q0) | ((u32)__bfloat16_as_ushort(q1) << 16);
                        if (F32O)
                            *(float2*)(out_f + base + nt*8) = make_float2(v0, v1);
                    }
                }
            }
        }
        __syncthreads();   // protect ring slots before next iteration's cp.async
    }
}

// ---------------- tail: 100 -> 3 on 256x256, + mean ----------------
__global__ __launch_bounds__(256) void tail_kernel(
    const float* __restrict__ in, const float* __restrict__ w,
    const float* __restrict__ b, float* __restrict__ out)
{
    __shared__ float w_s[2700];
    for (int i = threadIdx.x; i < 2700; i += 256) w_s[i] = w[i];
    __syncthreads();
    int idx = blockIdx.x*256 + threadIdx.x;
    int x = idx & 255, y = (idx >> 8) & 255, n = idx >> 16;
    float a0 = b[0], a1 = b[1], a2 = b[2];
    for (int ic = 0; ic < 100; ic++) {
        const float* ip = in + ((size_t)(n*100 + ic) * 256) * 256;
        #pragma unroll
        for (int dy = 0; dy < 3; dy++) {
            int gy = y + dy - 1;
            if ((unsigned)gy >= 256) continue;
            #pragma unroll
            for (int dx = 0; dx < 3; dx++) {
                int gx = x + dx - 1;
                if ((unsigned)gx >= 256) continue;
                float v = ip[gy*256 + gx];
                int t = ic*9 + dy*3 + dx;
                a0 += v * w_s[t];
                a1 += v * w_s[900 + t];
                a2 += v * w_s[1800 + t];
            }
        }
    }
    out[((size_t)(n*3 + 0)*256 + y)*256 + x] = a0 + 0.4488f*255.f;
    out[((size_t)(n*3 + 1)*256 + y)*256 + x] = a1 + 0.4371f*255.f;
    out[((size_t)(n*3 + 2)*256 + y)*256 + x] = a2 + 0.404f*255.f;
}

// ---------------- launch ----------------
extern "C" void kernel_launch(void* const* d_in, const int* in_sizes, int n_in,
                              void* d_out, int out_size)
{
    const float* x       = (const float*)d_in[0];
    const float* head_w  = (const float*)d_in[1];
    const float* head_b  = (const float*)d_in[2];
    const float* rb_w1   = (const float*)d_in[3];
    const float* rb_b1   = (const float*)d_in[4];
    const float* rb_w2   = (const float*)d_in[5];
    const float* rb_b2   = (const float*)d_in[6];
    const float* body_w  = (const float*)d_in[7];
    const float* body_b  = (const float*)d_in[8];
    const float* super_w = (const float*)d_in[9];
    const float* super_b = (const float*)d_in[10];
    const float* out_w   = (const float*)d_in[11];
    const float* out_b   = (const float*)d_in[12];
    float* out = (float*)d_out;

    bf16 *pHh,*pHl,*pAh,*pAl,*pBh,*pBl,*pW;
    float *pHf,*pAf,*pS;
    cudaGetSymbolAddress((void**)&pHh, g_Hh); cudaGetSymbolAddress((void**)&pHl, g_Hl);
    cudaGetSymbolAddress((void**)&pAh, g_Ah); cudaGetSymbolAddress((void**)&pAl, g_Al);
    cudaGetSymbolAddress((void**)&pBh, g_Bh); cudaGetSymbolAddress((void**)&pBl, g_Bl);
    cudaGetSymbolAddress((void**)&pHf, g_Hf); cudaGetSymbolAddress((void**)&pAf, g_Af);
    cudaGetSymbolAddress((void**)&pS,  g_S);  cudaGetSymbolAddress((void**)&pW,  g_Wp);

    cudaFuncSetAttribute(conv_mma<true,false,false,false>, cudaFuncAttributeMaxDynamicSharedMemorySize, DYN_SMEM);
    cudaFuncSetAttribute(conv_mma<false,true,true,false>,  cudaFuncAttributeMaxDynamicSharedMemorySize, DYN_SMEM);
    cudaFuncSetAttribute(conv_mma<false,true,false,false>, cudaFuncAttributeMaxDynamicSharedMemorySize, DYN_SMEM);
    cudaFuncSetAttribute(conv_mma<false,false,false,true>, cudaFuncAttributeMaxDynamicSharedMemorySize, DYN_SMEM);

    // weight prepack
    prepack_w<<<dim3(288,1,16), 256>>>(rb_w1, pW,                64, 64*64*9, 1);
    prepack_w<<<dim3(288,1,16), 256>>>(rb_w2, pW + 16*CHUNK_W,   64, 64*64*9, 1);
    prepack_w<<<dim3(288,1,1),  256>>>(body_w, pW + (size_t)32*CHUNK_W, 64, 0, 1);
    prepack_w<<<dim3(288,7,1),  256>>>(super_w, pW + (size_t)33*CHUNK_W, 400, 0, 7);

    head_tc<<<(N_IMG*HH*WW)/256, 256>>>(x, head_w, head_b, pHh, pHl, pHf);

    dim3 grid(8, 16, 1);
    const bf16 *ch = pHh, *cl = pHl;
    const float* cf = pHf;
    for (int i = 0; i < 16; i++) {
        conv_mma<true,false,false,false><<<grid, 128, DYN_SMEM>>>(
            ch, cl, pW + (size_t)i*CHUNK_W, rb_b1 + i*64, nullptr,
            pBh, pBl, nullptr, nullptr);
        conv_mma<false,true,true,false><<<grid, 128, DYN_SMEM>>>(
            pBh, pBl, pW + (size_t)(16+i)*CHUNK_W, rb_b2 + i*64, cf,
            pAh, pAl, pAf, nullptr);
        ch = pAh; cl = pAl; cf = pAf;
    }
    // body: conv(A) + H -> B planes
    conv_mma<false,true,false,false><<<grid, 128, DYN_SMEM>>>(
        pAh, pAl, pW + (size_t)32*CHUNK_W, body_b, pHf,
        pBh, pBl, nullptr, nullptr);
    // super: 7 chunks, fused pixel-shuffle -> g_S
    conv_mma<false,false,false,true><<<dim3(8, 16, 7), 128, DYN_SMEM>>>(
        pBh, pBl, pW + (size_t)33*CHUNK_W, super_b, nullptr,
        nullptr, nullptr, nullptr, pS);

    tail_kernel<<<(N_IMG*256*256)/256, 256>>>(pS, out_w, out_b, out);
}

// round 13
// speedup vs baseline: 2.3263x; 1.0096x over previous
#include <cuda_runtime.h>
#include <cuda_bf16.h>

typedef unsigned int u32;
typedef unsigned short u16;
typedef unsigned long long u64;
typedef __nv_bfloat16 bf16;

#define N_IMG 8
#define HH 128
#define WW 128
#define PLANE (N_IMG*HH*WW*64)
#define CHUNK_W (18*4096)          // bf16 elems per conv-chunk weight block (147456 B)
#define RING_SLOT 16896            // one row: 2 planes x 66 px x 128 B
#define DYN_SMEM (147456 + 4*RING_SLOT + 128)

// ---------------- scratch ----------------
__device__ bf16 g_Hh[PLANE], g_Hl[PLANE];
__device__ bf16 g_Ah[PLANE], g_Al[PLANE];
__device__ bf16 g_Bh[PLANE], g_Bl[PLANE];
__device__ float g_Hf[PLANE], g_Af[PLANE];
__device__ float g_S[N_IMG*100*256*256];
__device__ bf16 g_Wp[40*CHUNK_W];

// ---------------- helpers ----------------
__device__ __forceinline__ u32 smem_u32(const void* p){
    u32 a; asm("{ .reg .u64 t; cvta.to.shared.u64 t, %1; cvt.u32.u64 %0, t; }":"=r"(a):"l"(p)); return a;
}
__device__ __forceinline__ void ldsm4(u32* r, u32 addr){
    asm volatile("ldmatrix.sync.aligned.m8n8.x4.shared.b16 {%0,%1,%2,%3}, [%4];"
        : "=r"(r[0]),"=r"(r[1]),"=r"(r[2]),"=r"(r[3]) : "r"(addr));
}
__device__ __forceinline__ void ldsm4t(u32* r, u32 addr){
    asm volatile("ldmatrix.sync.aligned.m8n8.x4.trans.shared.b16 {%0,%1,%2,%3}, [%4];"
        : "=r"(r[0]),"=r"(r[1]),"=r"(r[2]),"=r"(r[3]) : "r"(addr));
}
__device__ __forceinline__ void mma_bf16(float* c, const u32* a, const u32* b){
    asm volatile("mma.sync.aligned.m16n8k16.row.col.f32.bf16.bf16.f32 "
        "{%0,%1,%2,%3}, {%4,%5,%6,%7}, {%8,%9}, {%0,%1,%2,%3};"
        : "+f"(c[0]),"+f"(c[1]),"+f"(c[2]),"+f"(c[3])
        : "r"(a[0]),"r"(a[1]),"r"(a[2]),"r"(a[3]), "r"(b[0]),"r"(b[1]));
}
__device__ __forceinline__ void cp16(u32 dst, const void* src, bool ok){
    int sz = ok ? 16 : 0;
    asm volatile("cp.async.cg.shared.global [%0], [%1], 16, %2;"
        :: "r"(dst), "l"(src), "r"(sz));
}
#define CP_COMMIT() asm volatile("cp.async.commit_group;" ::: "memory")
#define CP_WAIT(n)  asm volatile("cp.async.wait_group %0;" :: "n"(n) : "memory")

// ---------------- weight prepack ----------------
// per 64-oc chunk: 18 tiles [tap(9)][plane(2)], tile = [ic 64][oc 64] bf16,
// swizzled: byte = ic*128 + ((oc>>3)^(ic&7))*16 + (oc&7)*2
__global__ __launch_bounds__(256) void prepack_w(
    const float* __restrict__ src, bf16* __restrict__ dst,
    int cout, int conv_stride, int nchunks)
{
    int conv = blockIdx.z, chunk = blockIdx.y;
    int idx = blockIdx.x*256 + threadIdx.x;
    if (idx >= CHUNK_W) return;
    int tile = idx >> 12, r = idx & 4095;
    int oc = r >> 6, ic = r & 63;
    int tap = tile >> 1, pl = tile & 1;
    int dy = tap/3, dx = tap%3;
    int ocg = chunk*64 + oc;
    float wv = (ocg < cout) ? src[(size_t)conv*conv_stride + ((size_t)ocg*64 + ic)*9 + dy*3 + dx] : 0.f;
    bf16 h = __float2bfloat16(wv);
    bf16 v = pl ? __float2bfloat16(wv - __bfloat162float(h)) : h;
    int elem = tile*4096 + ic*64 + ((((oc>>3) ^ (ic&7)) << 3) | (oc & 7));
    dst[(size_t)(conv*nchunks + chunk)*CHUNK_W + elem] = v;
}

// ---------------- head: 3->64 fp32, out NHWC hi/lo/f32 ----------------
__global__ __launch_bounds__(256) void head_tc(
    const float* __restrict__ x, const float* __restrict__ w, const float* __restrict__ b,
    bf16* __restrict__ oh, bf16* __restrict__ ol, float* __restrict__ of)
{
    __shared__ float w_s[64*27];
    for (int i = threadIdx.x; i < 64*27; i += 256) w_s[i] = w[i];
    __syncthreads();
    int idx = blockIdx.x*256 + threadIdx.x;      // over 8*128*128
    int px = idx & 127, y = (idx >> 7) & 127, n = idx >> 14;
    const float mean[3] = {0.4488f*255.f, 0.4371f*255.f, 0.404f*255.f};
    float iv[27];
    #pragma unroll
    for (int ic = 0; ic < 3; ic++)
        #pragma unroll
        for (int dy = 0; dy < 3; dy++)
            #pragma unroll
            for (int dx = 0; dx < 3; dx++) {
                int gy = y + dy - 1, gx = px + dx - 1;
                float v = 0.f;
                if ((unsigned)gy < 128 && (unsigned)gx < 128)
                    v = x[((n*3 + ic)*128 + gy)*128 + gx] - mean[ic];
                iv[ic*9 + dy*3 + dx] = v;
            }
    size_t base = (size_t)idx * 64;
    for (int oc = 0; oc < 64; oc++) {
        float acc = b[oc];
        #pragma unroll
        for (int t = 0; t < 27; t++) acc += iv[t] * w_s[oc*27 + t];
        bf16 h = __float2bfloat16(acc);
        oh[base + oc] = h;
        ol[base + oc] = __float2bfloat16(acc - __bfloat162float(h));
        of[base + oc] = acc;
    }
}

// ---------------- mma.sync conv v4 ----------------
// CTA 128 thr (4 warps). Tile: 64 px (half-row) x 64 oc, strip of 16 rows.
// 2 output rows per tap sweep; two rows prefetched per iter (groups A/B).
// End-of-iter barrier removed: pre-dy2 barrier already orders dy=1 readers
// of slot yb&3 against next iteration's head cp.async to that slot.
template <bool RELU, bool RES, bool F32O, bool SHUF>
__global__ __launch_bounds__(128, 1) void conv_mma(
    const bf16* __restrict__ in_h, const bf16* __restrict__ in_l,
    const bf16* __restrict__ wp, const float* __restrict__ bias,
    const float* __restrict__ resf,
    bf16* __restrict__ out_h, bf16* __restrict__ out_l,
    float* __restrict__ out_f, float* __restrict__ out_s)
{
    extern __shared__ char dyn[];
    __shared__ float bias_s[64];
    const int tid = threadIdx.x, w = tid >> 5, lane = tid & 31;
    const int y0 = blockIdx.x * 16;
    const int half = blockIdx.y >> 3, n = blockIdx.y & 7;
    const int chunk = blockIdx.z;
    const int px0 = half * 64;

    u32 sb = smem_u32(dyn);
    u32 W_sa = (sb + 127) & ~127u;
    u32 ring_sa = W_sa + 147456;

    // async weight load (147456 B = 72 cp16/thread)
    {
        const char* wsrc = (const char*)(wp + (size_t)chunk * CHUNK_W);
        #pragma unroll 8
        for (int i = tid; i < 9216; i += 128)
            cp16(W_sa + i*16, wsrc + (size_t)i*16, true);
        if (tid < 64) bias_s[tid] = bias[chunk*64 + tid];
    }

    auto load_row = [&](int rg){
        u32 dst0 = ring_sa + (u32)(rg & 3) * RING_SLOT;
        bool rok = ((unsigned)rg < 128u);
        #pragma unroll 2
        for (int i = tid; i < 528; i += 128) {
            int px = i >> 3, c = i & 7;
            int pg = px0 + px - 1;
            bool ok = rok && ((unsigned)pg < 128u);
            size_t off = ok ? (((size_t)((n*128 + rg)*128 + pg))*64 + c*8) : 0;
            u32 d = dst0 + px*128 + ((c ^ (px & 7)) << 4);
            cp16(d, in_h + off, ok);
            cp16(d + 8448, in_l + off, ok);
        }
    };

    load_row(y0 - 1); load_row(y0); load_row(y0 + 1);
    CP_COMMIT();
    CP_WAIT(0);
    __syncthreads();

    const int bk = lane & 15, bsw = bk & 7, bh2 = lane >> 4;

    for (int yb = y0; yb < y0 + 16; yb += 2) {
        load_row(yb + 2);          // group A
        CP_COMMIT();

        float acc[2][8][4];
        #pragma unroll
        for (int rr = 0; rr < 2; rr++)
            #pragma unroll
            for (int t = 0; t < 8; t++)
                acc[rr][t][0]=acc[rr][t][1]=acc[rr][t][2]=acc[rr][t][3]=0.f;

        auto taps = [&](int dy, int s0, int s1){
            u32 sl0 = ring_sa + (u32)s0 * RING_SLOT;
            u32 sl1 = ring_sa + (u32)s1 * RING_SLOT;
            #pragma unroll 1
            for (int dx = 0; dx < 3; dx++) {
                int ar = w*16 + dx + bk;
                u32 arow0 = sl0 + ar*128, arow1 = sl1 + ar*128;
                u32 tapo = W_sa + (u32)((dy*3 + dx) * 2) * 8192u;
                #pragma unroll
                for (int kc = 0; kc < 4; kc++) {
                    u32 csel = (u32)((((kc << 1) | bh2) ^ (ar & 7)) << 4);
                    u32 a0h[4], a0l[4], a1h[4], a1l[4];
                    ldsm4(a0h, arow0 + csel);
                    ldsm4(a0l, arow0 + 8448 + csel);
                    ldsm4(a1h, arow1 + csel);
                    ldsm4(a1l, arow1 + 8448 + csel);
                    u32 brh = tapo + (u32)(kc*16 + bk) * 128u;
                    #pragma unroll
                    for (int np = 0; np < 4; np++) {
                        u32 co = (u32)(((np*2 + bh2) ^ bsw) << 4);
                        u32 bh[4], bl[4];
                        ldsm4t(bh, brh + co);
                        ldsm4t(bl, brh + 8192u + co);
                        mma_bf16(acc[0][np*2],   a0h, bh);
                        mma_bf16(acc[0][np*2+1], a0h, bh+2);
                        mma_bf16(acc[0][np*2],   a0l, bh);
                        mma_bf16(acc[0][np*2+1], a0l, bh+2);
                        mma_bf16(acc[0][np*2],   a0h, bl);
                        mma_bf16(acc[0][np*2+1], a0h, bl+2);
                        mma_bf16(acc[1][np*2],   a1h, bh);
                        mma_bf16(acc[1][np*2+1], a1h, bh+2);
                        mma_bf16(acc[1][np*2],   a1l, bh);
                        mma_bf16(acc[1][np*2+1], a1l, bh+2);
                        mma_bf16(acc[1][np*2],   a1h, bl);
                        mma_bf16(acc[1][np*2+1], a1h, bl+2);
                    }
                }
            }
        };

        // dy=0: input rows yb-1, yb
        taps(0, (yb-1)&3, yb&3);
        __syncthreads();           // dy=0 readers done -> slot (yb+3)&3 free
        load_row(yb + 3);          // group B
        CP_COMMIT();
        CP_WAIT(2);                // row yb+1 (B of prev iter) complete
        __syncthreads();
        // dy=1: input rows yb, yb+1
        taps(1, yb&3, (yb+1)&3);
        CP_WAIT(1);                // row yb+2 (A) complete
        __syncthreads();           // also orders dy=1 readers vs next iter head cp.async
        // dy=2: input rows yb+1, yb+2
        taps(2, (yb+1)&3, (yb+2)&3);

        // direct register epilogue
        const int cb = (lane & 3) * 2;
        #pragma unroll
        for (int rr = 0; rr < 2; rr++) {
            int yy = yb + rr;
            #pragma unroll
            for (int h = 0; h < 2; h++) {
                int pg = px0 + w*16 + (lane >> 2) + h*8;
                size_t base = ((size_t)((n*128 + yy)*128 + pg))*64 + cb;
                if (SHUF) {
                    #pragma unroll
                    for (int nt = 0; nt < 8; nt++) {
                        float v0 = acc[rr][nt][2*h]   + bias_s[nt*8 + cb];
                        float v1 = acc[rr][nt][2*h+1] + bias_s[nt*8 + cb + 1];
                        int oc0 = chunk*64 + nt*8 + cb;   // even; oc1 = oc0+1 shares (k,a)
                        if (oc0 < 400) {
                            int kk = oc0 >> 2, aa = (oc0 >> 1) & 1;
                            *(float2*)&out_s[((size_t)(n*100 + kk)*256 + (2*yy + aa))*256 + 2*pg] =
                                make_float2(v0, v1);
                        }
                    }
                } else {
                    #pragma unroll
                    for (int nt = 0; nt < 8; nt++) {
                        float v0 = acc[rr][nt][2*h]   + bias_s[nt*8 + cb];
                        float v1 = acc[rr][nt][2*h+1] + bias_s[nt*8 + cb + 1];
                        if (RELU) { v0 = fmaxf(v0, 0.f); v1 = fmaxf(v1, 0.f); }
                        if (RES) {
                            float2 r2 = *(const float2*)(resf + base + nt*8);
                            v0 += r2.x; v1 += r2.y;
                        }
                        bf16 h0 = __float2bfloat16(v0);
                        bf16 h1 = __float2bfloat16(v1);
                        bf16 q0 = __float2bfloat16(v0 - __bfloat162float(h0));
                        bf16 q1 = __float2bfloat16(v1 - __bfloat162float(h1));
                        *(u32*)(out_h + base + nt*8) =
                            (u32)__bfloat16_as_ushort(h0) | ((u32)__bfloat16_as_ushort(h1) << 16);
                        *(u32*)(out_l + base + nt*8) =
                            (u32)__bfloat16_as_ushort(q0) | ((u32)__bfloat16_as_ushort(q1) << 16);
                        if (F32O)
                            *(float2*)(out_f + base + nt*8) = make_float2(v0, v1);
                    }
                }
            }
        }
        // no trailing barrier: pre-dy2 barrier provides the WAR edge for slot yb&3
    }
}

// ---------------- tail v2: 100 -> 3 on 256x256, smem-tiled ----------------
#define TIC 20
__global__ __launch_bounds__(256) void tail_kernel(
    const float* __restrict__ in, const float* __restrict__ w,
    const float* __restrict__ b, float* __restrict__ out)
{
    __shared__ float w_s[2700];
    __shared__ float t_s[TIC][18][18];
    const int tx = threadIdx.x & 15, ty = threadIdx.x >> 4;
    const int x0 = blockIdx.x * 16, y0 = blockIdx.y * 16, n = blockIdx.z;

    for (int i = threadIdx.x; i < 2700; i += 256) w_s[i] = w[i];

    float a0 = b[0], a1 = b[1], a2 = b[2];
    for (int c0 = 0; c0 < 100; c0 += TIC) {
        __syncthreads();   // w_s ready (first pass) / t_s reuse (later passes)
        for (int i = threadIdx.x; i < TIC*324; i += 256) {
            int ic = i / 324, rem = i - ic*324;
            int r = rem / 18, c = rem - r*18;
            int gy = y0 + r - 1, gx = x0 + c - 1;
            float v = 0.f;
            if ((unsigned)gy < 256 && (unsigned)gx < 256)
                v = in[((size_t)(n*100 + c0 + ic) * 256 + gy) * 256 + gx];
            t_s[ic][r][c] = v;
        }
        __syncthreads();
        #pragma unroll 4
        for (int ic = 0; ic < TIC; ic++) {
            int t = (c0 + ic) * 9;
            #pragma unroll
            for (int dy = 0; dy < 3; dy++) {
                #pragma unroll
                for (int dx = 0; dx < 3; dx++) {
                    float v = t_s[ic][ty + dy][tx + dx];
                    int k = t + dy*3 + dx;
                    a0 += v * w_s[k];
                    a1 += v * w_s[900 + k];
                    a2 += v * w_s[1800 + k];
                }
            }
        }
    }
    int X = x0 + tx, Y = y0 + ty;
    out[((size_t)(n*3 + 0)*256 + Y)*256 + X] = a0 + 0.4488f*255.f;
    out[((size_t)(n*3 + 1)*256 + Y)*256 + X] = a1 + 0.4371f*255.f;
    out[((size_t)(n*3 + 2)*256 + Y)*256 + X] = a2 + 0.404f*255.f;
}

// ---------------- launch ----------------
extern "C" void kernel_launch(void* const* d_in, const int* in_sizes, int n_in,
                              void* d_out, int out_size)
{
    const float* x       = (const float*)d_in[0];
    const float* head_w  = (const float*)d_in[1];
    const float* head_b  = (const float*)d_in[2];
    const float* rb_w1   = (const float*)d_in[3];
    const float* rb_b1   = (const float*)d_in[4];
    const float* rb_w2   = (const float*)d_in[5];
    const float* rb_b2   = (const float*)d_in[6];
    const float* body_w  = (const float*)d_in[7];
    const float* body_b  = (const float*)d_in[8];
    const float* super_w = (const float*)d_in[9];
    const float* super_b = (const float*)d_in[10];
    const float* out_w   = (const float*)d_in[11];
    const float* out_b   = (const float*)d_in[12];
    float* out = (float*)d_out;

    bf16 *pHh,*pHl,*pAh,*pAl,*pBh,*pBl,*pW;
    float *pHf,*pAf,*pS;
    cudaGetSymbolAddress((void**)&pHh, g_Hh); cudaGetSymbolAddress((void**)&pHl, g_Hl);
    cudaGetSymbolAddress((void**)&pAh, g_Ah); cudaGetSymbolAddress((void**)&pAl, g_Al);
    cudaGetSymbolAddress((void**)&pBh, g_Bh); cudaGetSymbolAddress((void**)&pBl, g_Bl);
    cudaGetSymbolAddress((void**)&pHf, g_Hf); cudaGetSymbolAddress((void**)&pAf, g_Af);
    cudaGetSymbolAddress((void**)&pS,  g_S);  cudaGetSymbolAddress((void**)&pW,  g_Wp);

    cudaFuncSetAttribute(conv_mma<true,false,false,false>, cudaFuncAttributeMaxDynamicSharedMemorySize, DYN_SMEM);
    cudaFuncSetAttribute(conv_mma<false,true,true,false>,  cudaFuncAttributeMaxDynamicSharedMemorySize, DYN_SMEM);
    cudaFuncSetAttribute(conv_mma<false,true,false,false>, cudaFuncAttributeMaxDynamicSharedMemorySize, DYN_SMEM);
    cudaFuncSetAttribute(conv_mma<false,false,false,true>, cudaFuncAttributeMaxDynamicSharedMemorySize, DYN_SMEM);

    // weight prepack
    prepack_w<<<dim3(288,1,16), 256>>>(rb_w1, pW,                64, 64*64*9, 1);
    prepack_w<<<dim3(288,1,16), 256>>>(rb_w2, pW + 16*CHUNK_W,   64, 64*64*9, 1);
    prepack_w<<<dim3(288,1,1),  256>>>(body_w, pW + (size_t)32*CHUNK_W, 64, 0, 1);
    prepack_w<<<dim3(288,7,1),  256>>>(super_w, pW + (size_t)33*CHUNK_W, 400, 0, 7);

    head_tc<<<(N_IMG*HH*WW)/256, 256>>>(x, head_w, head_b, pHh, pHl, pHf);

    dim3 grid(8, 16, 1);
    const bf16 *ch = pHh, *cl = pHl;
    const float* cf = pHf;
    for (int i = 0; i < 16; i++) {
        conv_mma<true,false,false,false><<<grid, 128, DYN_SMEM>>>(
            ch, cl, pW + (size_t)i*CHUNK_W, rb_b1 + i*64, nullptr,
            pBh, pBl, nullptr, nullptr);
        conv_mma<false,true,true,false><<<grid, 128, DYN_SMEM>>>(
            pBh, pBl, pW + (size_t)(16+i)*CHUNK_W, rb_b2 + i*64, cf,
            pAh, pAl, pAf, nullptr);
        ch = pAh; cl = pAl; cf = pAf;
    }
    // body: conv(A) + H -> B planes
    conv_mma<false,true,false,false><<<grid, 128, DYN_SMEM>>>(
        pAh, pAl, pW + (size_t)32*CHUNK_W, body_b, pHf,
        pBh, pBl, nullptr, nullptr);
    // super: 7 chunks, fused pixel-shuffle -> g_S
    conv_mma<false,false,false,true><<<dim3(8, 16, 7), 128, DYN_SMEM>>>(
        pBh, pBl, pW + (size_t)33*CHUNK_W, super_b, nullptr,
        nullptr, nullptr, nullptr, pS);

    tail_kernel<<<dim3(16, 16, N_IMG), 256>>>(pS, out_w, out_b, out);
}

// round 16
// speedup vs baseline: 2.3291x; 1.0012x over previous
#include <cuda_runtime.h>
#include <cuda_bf16.h>

typedef unsigned int u32;
typedef unsigned short u16;
typedef unsigned long long u64;
typedef __nv_bfloat16 bf16;

#define N_IMG 8
#define HH 128
#define WW 128
#define PLANE (N_IMG*HH*WW*64)
#define CHUNK_W (18*4096)          // bf16 elems per conv-chunk weight block (147456 B)
#define RING_SLOT 16896            // one row: 2 planes x 66 px x 128 B
#define DYN_SMEM (147456 + 4*RING_SLOT + 128)

// ---------------- scratch ----------------
__device__ bf16 g_Hh[PLANE], g_Hl[PLANE];
__device__ bf16 g_Ah[PLANE], g_Al[PLANE];
__device__ bf16 g_Bh[PLANE], g_Bl[PLANE];
__device__ float g_Hf[PLANE], g_Af[PLANE];
__device__ float g_S[N_IMG*100*256*256];
__device__ bf16 g_Wp[40*CHUNK_W];

// ---------------- helpers ----------------
__device__ __forceinline__ u32 smem_u32(const void* p){
    u32 a; asm("{ .reg .u64 t; cvta.to.shared.u64 t, %1; cvt.u32.u64 %0, t; }":"=r"(a):"l"(p)); return a;
}
__device__ __forceinline__ void ldsm4(u32* r, u32 addr){
    asm volatile("ldmatrix.sync.aligned.m8n8.x4.shared.b16 {%0,%1,%2,%3}, [%4];"
        : "=r"(r[0]),"=r"(r[1]),"=r"(r[2]),"=r"(r[3]) : "r"(addr));
}
__device__ __forceinline__ void ldsm4t(u32* r, u32 addr){
    asm volatile("ldmatrix.sync.aligned.m8n8.x4.trans.shared.b16 {%0,%1,%2,%3}, [%4];"
        : "=r"(r[0]),"=r"(r[1]),"=r"(r[2]),"=r"(r[3]) : "r"(addr));
}
__device__ __forceinline__ void mma_bf16(float* c, const u32* a, const u32* b){
    asm volatile("mma.sync.aligned.m16n8k16.row.col.f32.bf16.bf16.f32 "
        "{%0,%1,%2,%3}, {%4,%5,%6,%7}, {%8,%9}, {%0,%1,%2,%3};"
        : "+f"(c[0]),"+f"(c[1]),"+f"(c[2]),"+f"(c[3])
        : "r"(a[0]),"r"(a[1]),"r"(a[2]),"r"(a[3]), "r"(b[0]),"r"(b[1]));
}
__device__ __forceinline__ void cp16(u32 dst, const void* src, bool ok){
    int sz = ok ? 16 : 0;
    asm volatile("cp.async.cg.shared.global [%0], [%1], 16, %2;"
        :: "r"(dst), "l"(src), "r"(sz));
}
#define CP_COMMIT() asm volatile("cp.async.commit_group;" ::: "memory")
#define CP_WAIT(n)  asm volatile("cp.async.wait_group %0;" :: "n"(n) : "memory")

// ---------------- weight prepack ----------------
__global__ __launch_bounds__(256) void prepack_w(
    const float* __restrict__ src, bf16* __restrict__ dst,
    int cout, int conv_stride, int nchunks)
{
    int conv = blockIdx.z, chunk = blockIdx.y;
    int idx = blockIdx.x*256 + threadIdx.x;
    if (idx >= CHUNK_W) return;
    int tile = idx >> 12, r = idx & 4095;
    int oc = r >> 6, ic = r & 63;
    int tap = tile >> 1, pl = tile & 1;
    int dy = tap/3, dx = tap%3;
    int ocg = chunk*64 + oc;
    float wv = (ocg < cout) ? src[(size_t)conv*conv_stride + ((size_t)ocg*64 + ic)*9 + dy*3 + dx] : 0.f;
    bf16 h = __float2bfloat16(wv);
    bf16 v = pl ? __float2bfloat16(wv - __bfloat162float(h)) : h;
    int elem = tile*4096 + ic*64 + ((((oc>>3) ^ (ic&7)) << 3) | (oc & 7));
    dst[(size_t)(conv*nchunks + chunk)*CHUNK_W + elem] = v;
}

// ---------------- head: 3->64 fp32, out NHWC hi/lo/f32 ----------------
__global__ __launch_bounds__(256) void head_tc(
    const float* __restrict__ x, const float* __restrict__ w, const float* __restrict__ b,
    bf16* __restrict__ oh, bf16* __restrict__ ol, float* __restrict__ of)
{
    __shared__ float w_s[64*27];
    for (int i = threadIdx.x; i < 64*27; i += 256) w_s[i] = w[i];
    __syncthreads();
    int idx = blockIdx.x*256 + threadIdx.x;      // over 8*128*128
    int px = idx & 127, y = (idx >> 7) & 127, n = idx >> 14;
    const float mean[3] = {0.4488f*255.f, 0.4371f*255.f, 0.404f*255.f};
    float iv[27];
    #pragma unroll
    for (int ic = 0; ic < 3; ic++)
        #pragma unroll
        for (int dy = 0; dy < 3; dy++)
            #pragma unroll
            for (int dx = 0; dx < 3; dx++) {
                int gy = y + dy - 1, gx = px + dx - 1;
                float v = 0.f;
                if ((unsigned)gy < 128 && (unsigned)gx < 128)
                    v = x[((n*3 + ic)*128 + gy)*128 + gx] - mean[ic];
                iv[ic*9 + dy*3 + dx] = v;
            }
    size_t base = (size_t)idx * 64;
    for (int oc = 0; oc < 64; oc++) {
        float acc = b[oc];
        #pragma unroll
        for (int t = 0; t < 27; t++) acc += iv[t] * w_s[oc*27 + t];
        bf16 h = __float2bfloat16(acc);
        oh[base + oc] = h;
        ol[base + oc] = __float2bfloat16(acc - __bfloat162float(h));
        of[base + oc] = acc;
    }
}

// ---------------- mma.sync conv v5 ----------------
// v4 + (a) round-robin MMA ordering across the 4 independent accumulators
// (dependent-pair spacing 4 issues = 32cyc > HMMA accum latency), and
// (b) B-fragment double-buffer: np+1's ldsm4t issued before np's MMA block.
template <bool RELU, bool RES, bool F32O, bool SHUF>
__global__ __launch_bounds__(128, 1) void conv_mma(
    const bf16* __restrict__ in_h, const bf16* __restrict__ in_l,
    const bf16* __restrict__ wp, const float* __restrict__ bias,
    const float* __restrict__ resf,
    bf16* __restrict__ out_h, bf16* __restrict__ out_l,
    float* __restrict__ out_f, float* __restrict__ out_s)
{
    extern __shared__ char dyn[];
    __shared__ float bias_s[64];
    const int tid = threadIdx.x, w = tid >> 5, lane = tid & 31;
    const int y0 = blockIdx.x * 16;
    const int half = blockIdx.y >> 3, n = blockIdx.y & 7;
    const int chunk = blockIdx.z;
    const int px0 = half * 64;

    u32 sb = smem_u32(dyn);
    u32 W_sa = (sb + 127) & ~127u;
    u32 ring_sa = W_sa + 147456;

    // async weight load (147456 B = 72 cp16/thread)
    {
        const char* wsrc = (const char*)(wp + (size_t)chunk * CHUNK_W);
        #pragma unroll 8
        for (int i = tid; i < 9216; i += 128)
            cp16(W_sa + i*16, wsrc + (size_t)i*16, true);
        if (tid < 64) bias_s[tid] = bias[chunk*64 + tid];
    }

    auto load_row = [&](int rg){
        u32 dst0 = ring_sa + (u32)(rg & 3) * RING_SLOT;
        bool rok = ((unsigned)rg < 128u);
        #pragma unroll 2
        for (int i = tid; i < 528; i += 128) {
            int px = i >> 3, c = i & 7;
            int pg = px0 + px - 1;
            bool ok = rok && ((unsigned)pg < 128u);
            size_t off = ok ? (((size_t)((n*128 + rg)*128 + pg))*64 + c*8) : 0;
            u32 d = dst0 + px*128 + ((c ^ (px & 7)) << 4);
            cp16(d, in_h + off, ok);
            cp16(d + 8448, in_l + off, ok);
        }
    };

    load_row(y0 - 1); load_row(y0); load_row(y0 + 1);
    CP_COMMIT();
    CP_WAIT(0);
    __syncthreads();

    const int bk = lane & 15, bsw = bk & 7, bh2 = lane >> 4;

    for (int yb = y0; yb < y0 + 16; yb += 2) {
        load_row(yb + 2);          // group A
        CP_COMMIT();

        float acc[2][8][4];
        #pragma unroll
        for (int rr = 0; rr < 2; rr++)
            #pragma unroll
            for (int t = 0; t < 8; t++)
                acc[rr][t][0]=acc[rr][t][1]=acc[rr][t][2]=acc[rr][t][3]=0.f;

        auto taps = [&](int dy, int s0, int s1){
            u32 sl0 = ring_sa + (u32)s0 * RING_SLOT;
            u32 sl1 = ring_sa + (u32)s1 * RING_SLOT;
            #pragma unroll 1
            for (int dx = 0; dx < 3; dx++) {
                int ar = w*16 + dx + bk;
                u32 arow0 = sl0 + ar*128, arow1 = sl1 + ar*128;
                u32 tapo = W_sa + (u32)((dy*3 + dx) * 2) * 8192u;
                #pragma unroll
                for (int kc = 0; kc < 4; kc++) {
                    u32 csel = (u32)((((kc << 1) | bh2) ^ (ar & 7)) << 4);
                    u32 a0h[4], a0l[4], a1h[4], a1l[4];
                    ldsm4(a0h, arow0 + csel);
                    ldsm4(a0l, arow0 + 8448 + csel);
                    ldsm4(a1h, arow1 + csel);
                    ldsm4(a1l, arow1 + 8448 + csel);
                    u32 brh = tapo + (u32)(kc*16 + bk) * 128u;
                    u32 bfh[2][4], bfl[2][4];
                    {
                        u32 co = (u32)((bh2 ^ bsw) << 4);
                        ldsm4t(bfh[0], brh + co);
                        ldsm4t(bfl[0], brh + 8192u + co);
                    }
                    #pragma unroll
                    for (int np = 0; np < 4; np++) {
                        const int cur = np & 1, nxt = cur ^ 1;
                        if (np < 3) {
                            u32 co = (u32)(((((np+1)*2) + bh2) ^ bsw) << 4);
                            ldsm4t(bfh[nxt], brh + co);
                            ldsm4t(bfl[nxt], brh + 8192u + co);
                        }
                        u32* bh_ = bfh[cur];
                        u32* bl_ = bfl[cur];
                        // round-robin over 4 independent accumulators
                        mma_bf16(acc[0][np*2],   a0h, bh_);
                        mma_bf16(acc[0][np*2+1], a0h, bh_+2);
                        mma_bf16(acc[1][np*2],   a1h, bh_);
                        mma_bf16(acc[1][np*2+1], a1h, bh_+2);
                        mma_bf16(acc[0][np*2],   a0l, bh_);
                        mma_bf16(acc[0][np*2+1], a0l, bh_+2);
                        mma_bf16(acc[1][np*2],   a1l, bh_);
                        mma_bf16(acc[1][np*2+1], a1l, bh_+2);
                        mma_bf16(acc[0][np*2],   a0h, bl_);
                        mma_bf16(acc[0][np*2+1], a0h, bl_+2);
                        mma_bf16(acc[1][np*2],   a1h, bl_);
                        mma_bf16(acc[1][np*2+1], a1h, bl_+2);
                    }
                }
            }
        };

        // dy=0: input rows yb-1, yb
        taps(0, (yb-1)&3, yb&3);
        __syncthreads();           // dy=0 readers done -> slot (yb+3)&3 free
        load_row(yb + 3);          // group B
        CP_COMMIT();
        CP_WAIT(2);                // row yb+1 (B of prev iter) complete
        __syncthreads();
        // dy=1: input rows yb, yb+1
        taps(1, yb&3, (yb+1)&3);
        CP_WAIT(1);                // row yb+2 (A) complete
        __syncthreads();           // also orders dy=1 readers vs next iter head cp.async
        // dy=2: input rows yb+1, yb+2
        taps(2, (yb+1)&3, (yb+2)&3);

        // direct register epilogue
        const int cb = (lane & 3) * 2;
        #pragma unroll
        for (int rr = 0; rr < 2; rr++) {
            int yy = yb + rr;
            #pragma unroll
            for (int h = 0; h < 2; h++) {
                int pg = px0 + w*16 + (lane >> 2) + h*8;
                size_t base = ((size_t)((n*128 + yy)*128 + pg))*64 + cb;
                if (SHUF) {
                    #pragma unroll
                    for (int nt = 0; nt < 8; nt++) {
                        float v0 = acc[rr][nt][2*h]   + bias_s[nt*8 + cb];
                        float v1 = acc[rr][nt][2*h+1] + bias_s[nt*8 + cb + 1];
                        int oc0 = chunk*64 + nt*8 + cb;   // even; oc1 = oc0+1 shares (k,a)
                        if (oc0 < 400) {
                            int kk = oc0 >> 2, aa = (oc0 >> 1) & 1;
                            *(float2*)&out_s[((size_t)(n*100 + kk)*256 + (2*yy + aa))*256 + 2*pg] =
                                make_float2(v0, v1);
                        }
                    }
                } else {
                    #pragma unroll
                    for (int nt = 0; nt < 8; nt++) {
                        float v0 = acc[rr][nt][2*h]   + bias_s[nt*8 + cb];
                        float v1 = acc[rr][nt][2*h+1] + bias_s[nt*8 + cb + 1];
                        if (RELU) { v0 = fmaxf(v0, 0.f); v1 = fmaxf(v1, 0.f); }
                        if (RES) {
                            float2 r2 = *(const float2*)(resf + base + nt*8);
                            v0 += r2.x; v1 += r2.y;
                        }
                        bf16 h0 = __float2bfloat16(v0);
                        bf16 h1 = __float2bfloat16(v1);
                        bf16 q0 = __float2bfloat16(v0 - __bfloat162float(h0));
                        bf16 q1 = __float2bfloat16(v1 - __bfloat162float(h1));
                        *(u32*)(out_h + base + nt*8) =
                            (u32)__bfloat16_as_ushort(h0) | ((u32)__bfloat16_as_ushort(h1) << 16);
                        *(u32*)(out_l + base + nt*8) =
                            (u32)__bfloat16_as_ushort(q0) | ((u32)__bfloat16_as_ushort(q1) << 16);
                        if (F32O)
                            *(float2*)(out_f + base + nt*8) = make_float2(v0, v1);
                    }
                }
            }
        }
        // no trailing barrier: pre-dy2 barrier provides the WAR edge for slot yb&3
    }
}

// ---------------- tail v2: 100 -> 3 on 256x256, smem-tiled ----------------
#define TIC 20
__global__ __launch_bounds__(256) void tail_kernel(
    const float* __restrict__ in, const float* __restrict__ w,
    const float* __restrict__ b, float* __restrict__ out)
{
    __shared__ float w_s[2700];
    __shared__ float t_s[TIC][18][18];
    const int tx = threadIdx.x & 15, ty = threadIdx.x >> 4;
    const int x0 = blockIdx.x * 16, y0 = blockIdx.y * 16, n = blockIdx.z;

    for (int i = threadIdx.x; i < 2700; i += 256) w_s[i] = w[i];

    float a0 = b[0], a1 = b[1], a2 = b[2];
    for (int c0 = 0; c0 < 100; c0 += TIC) {
        __syncthreads();
        for (int i = threadIdx.x; i < TIC*324; i += 256) {
            int ic = i / 324, rem = i - ic*324;
            int r = rem / 18, c = rem - r*18;
            int gy = y0 + r - 1, gx = x0 + c - 1;
            float v = 0.f;
            if ((unsigned)gy < 256 && (unsigned)gx < 256)
                v = in[((size_t)(n*100 + c0 + ic) * 256 + gy) * 256 + gx];
            t_s[ic][r][c] = v;
        }
        __syncthreads();
        #pragma unroll 4
        for (int ic = 0; ic < TIC; ic++) {
            int t = (c0 + ic) * 9;
            #pragma unroll
            for (int dy = 0; dy < 3; dy++) {
                #pragma unroll
                for (int dx = 0; dx < 3; dx++) {
                    float v = t_s[ic][ty + dy][tx + dx];
                    int k = t + dy*3 + dx;
                    a0 += v * w_s[k];
                    a1 += v * w_s[900 + k];
                    a2 += v * w_s[1800 + k];
                }
            }
        }
    }
    int X = x0 + tx, Y = y0 + ty;
    out[((size_t)(n*3 + 0)*256 + Y)*256 + X] = a0 + 0.4488f*255.f;
    out[((size_t)(n*3 + 1)*256 + Y)*256 + X] = a1 + 0.4371f*255.f;
    out[((size_t)(n*3 + 2)*256 + Y)*256 + X] = a2 + 0.404f*255.f;
}

// ---------------- launch ----------------
extern "C" void kernel_launch(void* const* d_in, const int* in_sizes, int n_in,
                              void* d_out, int out_size)
{
    const float* x       = (const float*)d_in[0];
    const float* head_w  = (const float*)d_in[1];
    const float* head_b  = (const float*)d_in[2];
    const float* rb_w1   = (const float*)d_in[3];
    const float* rb_b1   = (const float*)d_in[4];
    const float* rb_w2   = (const float*)d_in[5];
    const float* rb_b2   = (const float*)d_in[6];
    const float* body_w  = (const float*)d_in[7];
    const float* body_b  = (const float*)d_in[8];
    const float* super_w = (const float*)d_in[9];
    const float* super_b = (const float*)d_in[10];
    const float* out_w   = (const float*)d_in[11];
    const float* out_b   = (const float*)d_in[12];
    float* out = (float*)d_out;

    bf16 *pHh,*pHl,*pAh,*pAl,*pBh,*pBl,*pW;
    float *pHf,*pAf,*pS;
    cudaGetSymbolAddress((void**)&pHh, g_Hh); cudaGetSymbolAddress((void**)&pHl, g_Hl);
    cudaGetSymbolAddress((void**)&pAh, g_Ah); cudaGetSymbolAddress((void**)&pAl, g_Al);
    cudaGetSymbolAddress((void**)&pBh, g_Bh); cudaGetSymbolAddress((void**)&pBl, g_Bl);
    cudaGetSymbolAddress((void**)&pHf, g_Hf); cudaGetSymbolAddress((void**)&pAf, g_Af);
    cudaGetSymbolAddress((void**)&pS,  g_S);  cudaGetSymbolAddress((void**)&pW,  g_Wp);

    cudaFuncSetAttribute(conv_mma<true,false,false,false>, cudaFuncAttributeMaxDynamicSharedMemorySize, DYN_SMEM);
    cudaFuncSetAttribute(conv_mma<false,true,true,false>,  cudaFuncAttributeMaxDynamicSharedMemorySize, DYN_SMEM);
    cudaFuncSetAttribute(conv_mma<false,true,false,false>, cudaFuncAttributeMaxDynamicSharedMemorySize, DYN_SMEM);
    cudaFuncSetAttribute(conv_mma<false,false,false,true>, cudaFuncAttributeMaxDynamicSharedMemorySize, DYN_SMEM);

    // weight prepack
    prepack_w<<<dim3(288,1,16), 256>>>(rb_w1, pW,                64, 64*64*9, 1);
    prepack_w<<<dim3(288,1,16), 256>>>(rb_w2, pW + 16*CHUNK_W,   64, 64*64*9, 1);
    prepack_w<<<dim3(288,1,1),  256>>>(body_w, pW + (size_t)32*CHUNK_W, 64, 0, 1);
    prepack_w<<<dim3(288,7,1),  256>>>(super_w, pW + (size_t)33*CHUNK_W, 400, 0, 7);

    head_tc<<<(N_IMG*HH*WW)/256, 256>>>(x, head_w, head_b, pHh, pHl, pHf);

    dim3 grid(8, 16, 1);
    const bf16 *ch = pHh, *cl = pHl;
    const float* cf = pHf;
    for (int i = 0; i < 16; i++) {
        conv_mma<true,false,false,false><<<grid, 128, DYN_SMEM>>>(
            ch, cl, pW + (size_t)i*CHUNK_W, rb_b1 + i*64, nullptr,
            pBh, pBl, nullptr, nullptr);
        conv_mma<false,true,true,false><<<grid, 128, DYN_SMEM>>>(
            pBh, pBl, pW + (size_t)(16+i)*CHUNK_W, rb_b2 + i*64, cf,
            pAh, pAl, pAf, nullptr);
        ch = pAh; cl = pAl; cf = pAf;
    }
    // body: conv(A) + H -> B planes
    conv_mma<false,true,false,false><<<grid, 128, DYN_SMEM>>>(
        pAh, pAl, pW + (size_t)32*CHUNK_W, body_b, pHf,
        pBh, pBl, nullptr, nullptr);
    // super: 7 chunks, fused pixel-shuffle -> g_S
    conv_mma<false,false,false,true><<<dim3(8, 16, 7), 128, DYN_SMEM>>>(
        pBh, pBl, pW + (size_t)33*CHUNK_W, super_b, nullptr,
        nullptr, nullptr, nullptr, pS);

    tail_kernel<<<dim3(16, 16, N_IMG), 256>>>(pS, out_w, out_b, out);
}